// round 10
// baseline (speedup 1.0000x reference)
#include <cuda_runtime.h>
#include <cuda_bf16.h>
#include <cstdint>
#include <math.h>

// Problem constants
#define BB   2
#define SS   2048
#define DD   768
#define HH   12
#define HDIM 64
#define HALFW 64
#define NEGV -1000000000.0f

// ---------------------------------------------------------------------------
// Scratch (no cudaMalloc allowed)
// ---------------------------------------------------------------------------
__device__ float g_qkv[BB * SS * 3 * DD];            // fp32 qkv  (4096 x 2304)
__device__ __nv_bfloat16 g_xhi[BB * SS * DD];        // x split
__device__ __nv_bfloat16 g_xlo[BB * SS * DD];
__device__ __nv_bfloat16 g_wqh[3 * DD * DD];         // Wqkv^T split (2304 x 768)
__device__ __nv_bfloat16 g_wql[3 * DD * DD];
__device__ __nv_bfloat16 g_woh[DD * DD];             // Wo^T split (768 x 768)
__device__ __nv_bfloat16 g_wol[DD * DD];
__device__ __nv_bfloat16 g_ahi[BB * SS * DD];        // attn out split (written by attn)
__device__ __nv_bfloat16 g_alo[BB * SS * DD];

// ---------------------------------------------------------------------------
// Common helpers
// ---------------------------------------------------------------------------
__device__ __forceinline__ uint32_t smem_u32(const void* p) {
    uint32_t a;
    asm("{ .reg .u64 t; cvta.to.shared.u64 t, %1; cvt.u32.u64 %0, t; }"
        : "=r"(a) : "l"(p));
    return a;
}

__device__ __forceinline__ void cp_async16(uint32_t dst, const void* src) {
    asm volatile("cp.async.cg.shared.global [%0], [%1], 16;" :: "r"(dst), "l"(src));
}
#define CP_COMMIT() asm volatile("cp.async.commit_group;" ::: "memory")
#define CP_WAIT1()  asm volatile("cp.async.wait_group 1;" ::: "memory")
#define CP_WAIT2()  asm volatile("cp.async.wait_group 2;" ::: "memory")

#define LDSM_X4(r0, r1, r2, r3, addr) \
    asm volatile("ldmatrix.sync.aligned.m8n8.x4.shared.b16 {%0,%1,%2,%3}, [%4];" \
                 : "=r"(r0), "=r"(r1), "=r"(r2), "=r"(r3) : "r"(addr))
#define LDSM_X2(r0, r1, addr) \
    asm volatile("ldmatrix.sync.aligned.m8n8.x2.shared.b16 {%0,%1}, [%2];" \
                 : "=r"(r0), "=r"(r1) : "r"(addr))
#define LDSM_X2T(r0, r1, addr) \
    asm volatile("ldmatrix.sync.aligned.m8n8.x2.trans.shared.b16 {%0,%1}, [%2];" \
                 : "=r"(r0), "=r"(r1) : "r"(addr))

__device__ __forceinline__ void mma16816(float* c, const uint32_t* a, const uint32_t* b)
{
    asm volatile(
        "mma.sync.aligned.m16n8k16.row.col.f32.bf16.bf16.f32 "
        "{%0,%1,%2,%3}, {%4,%5,%6,%7}, {%8,%9}, {%0,%1,%2,%3};"
        : "+f"(c[0]), "+f"(c[1]), "+f"(c[2]), "+f"(c[3])
        : "r"(a[0]), "r"(a[1]), "r"(a[2]), "r"(a[3]), "r"(b[0]), "r"(b[1]));
}

__device__ __forceinline__ void split2(float a, float b, uint32_t& hi, uint32_t& lo)
{
    __nv_bfloat16 ha = __float2bfloat16(a), hb = __float2bfloat16(b);
    __nv_bfloat16 la = __float2bfloat16(a - __bfloat162float(ha));
    __nv_bfloat16 lb = __float2bfloat16(b - __bfloat162float(hb));
    hi = ((uint32_t)__bfloat16_as_ushort(hb) << 16) | (uint32_t)__bfloat16_as_ushort(ha);
    lo = ((uint32_t)__bfloat16_as_ushort(lb) << 16) | (uint32_t)__bfloat16_as_ushort(la);
}

// ---------------------------------------------------------------------------
// Split / transpose-split conversion kernels
// ---------------------------------------------------------------------------
__global__ __launch_bounds__(256) void split_kernel(
    const float* __restrict__ in, __nv_bfloat16* __restrict__ hi,
    __nv_bfloat16* __restrict__ lo, int n)
{
    int i = blockIdx.x * 256 + threadIdx.x;
    if (i < n) {
        float v = in[i];
        __nv_bfloat16 h = __float2bfloat16(v);
        hi[i] = h;
        lo[i] = __float2bfloat16(v - __bfloat162float(h));
    }
}

__global__ __launch_bounds__(256) void splitT_kernel(
    const float* __restrict__ in, __nv_bfloat16* __restrict__ hiT,
    __nv_bfloat16* __restrict__ loT, int K, int N)
{
    __shared__ float t[32][33];
    const int k0 = blockIdx.y * 32, n0 = blockIdx.x * 32;
    const int tx = threadIdx.x, ty = threadIdx.y;   // 32 x 8
    #pragma unroll
    for (int i = 0; i < 32; i += 8)
        t[ty + i][tx] = in[(size_t)(k0 + ty + i) * N + n0 + tx];
    __syncthreads();
    #pragma unroll
    for (int i = 0; i < 32; i += 8) {
        float v = t[tx][ty + i];
        __nv_bfloat16 h = __float2bfloat16(v);
        size_t o = (size_t)(n0 + ty + i) * K + k0 + tx;
        hiT[o] = h;
        loT[o] = __float2bfloat16(v - __bfloat162float(h));
    }
}

// ---------------------------------------------------------------------------
// bf16x3 mma.sync GEMM, 4-stage cp.async pipeline, one barrier per iter.
// C[M,N] = A[M,K] @ Bt[N,K]^T, fp32 accumulate.
// Block tile 128x128x16 per stage, 8 warps (2m x 4n), warp tile 64x32.
// M%128==0, N%128==0, K%16==0, K/16 >= 3.
// ---------------------------------------------------------------------------
#define SMS 24                                  // smem row stride (16 + 8 pad)
#define TILE_BYTES (128 * SMS * 2)              // 6144
#define STAGE_BYTES (4 * TILE_BYTES)            // 24576 (Ah, Al, Bh, Bl)
#define GEMM_SMEM (4 * STAGE_BYTES)             // 98304

__global__ __launch_bounds__(256) void gemm_bf16x3_kernel(
    const __nv_bfloat16* __restrict__ Ahi, const __nv_bfloat16* __restrict__ Alo,
    const __nv_bfloat16* __restrict__ Bthi, const __nv_bfloat16* __restrict__ Btlo,
    float* __restrict__ C, int M, int N, int K)
{
    extern __shared__ __align__(128) char smem[];
    const uint32_t smem_base = smem_u32(smem);

    const int tid = threadIdx.x;
    const int wid = tid >> 5, lane = tid & 31;
    const int g = lane >> 2, tg = lane & 3;
    const int wm = wid >> 2, wn = wid & 3;        // 2 x 4 warp grid
    const int mbase = wm * 64, nbase = wn * 32;
    const int bm = blockIdx.y * 128, bn = blockIdx.x * 128;

    const __nv_bfloat16* srcs[4] = {
        Ahi + (size_t)bm * K, Alo + (size_t)bm * K,
        Bthi + (size_t)bn * K, Btlo + (size_t)bn * K };

    const int niter = K >> 4;

    // cp.async staging: per tile 128 rows x 2 chunks of 16B; 1 chunk/thread/tile
    const int row = tid >> 1, q = tid & 1;
    const uint32_t st_off = (uint32_t)(row * (SMS * 2) + q * 16);
    const size_t g_off = (size_t)row * K + q * 8;

    // ldmatrix lane address (shared by A x4 and paired-B x4)
    const uint32_t ab_lane = (uint32_t)((lane & 15) * (SMS * 2) + ((lane >> 4) << 4));

    float acc[4][4][4];
    #pragma unroll
    for (int i = 0; i < 4; i++)
        #pragma unroll
        for (int j = 0; j < 4; j++)
            #pragma unroll
            for (int c = 0; c < 4; c++) acc[i][j][c] = 0.f;

    // ---- prologue: prefetch stages 0..2 ----
    #pragma unroll
    for (int p = 0; p < 3; p++) {
        const uint32_t db = smem_base + (uint32_t)p * STAGE_BYTES;
        const int k0 = p << 4;
        #pragma unroll
        for (int t = 0; t < 4; t++)
            cp_async16(db + (uint32_t)t * TILE_BYTES + st_off, srcs[t] + g_off + k0);
        CP_COMMIT();
    }

    for (int it = 0; it < niter; it++) {
        CP_WAIT2();
        __syncthreads();

        const uint32_t sbuf = smem_base + (uint32_t)(it & 3) * STAGE_BYTES;

        uint32_t ah[4][4], al[4][4], bh[4][2], bl[4][2];
        #pragma unroll
        for (int mt = 0; mt < 4; mt++) {
            const uint32_t ro = ab_lane + (uint32_t)((mbase + mt * 16) * (SMS * 2));
            LDSM_X4(ah[mt][0], ah[mt][1], ah[mt][2], ah[mt][3], sbuf + ro);
            LDSM_X4(al[mt][0], al[mt][1], al[mt][2], al[mt][3], sbuf + TILE_BYTES + ro);
        }
        #pragma unroll
        for (int pr = 0; pr < 2; pr++) {
            const uint32_t ro = ab_lane + (uint32_t)((nbase + pr * 16) * (SMS * 2));
            uint32_t r0, r1, r2, r3;
            LDSM_X4(r0, r1, r2, r3, sbuf + 2 * TILE_BYTES + ro);
            bh[pr * 2][0] = r0; bh[pr * 2][1] = r2;
            bh[pr * 2 + 1][0] = r1; bh[pr * 2 + 1][1] = r3;
            LDSM_X4(r0, r1, r2, r3, sbuf + 3 * TILE_BYTES + ro);
            bl[pr * 2][0] = r0; bl[pr * 2][1] = r2;
            bl[pr * 2 + 1][0] = r1; bl[pr * 2 + 1][1] = r3;
        }

        #pragma unroll
        for (int mt = 0; mt < 4; mt++)
            #pragma unroll
            for (int nt = 0; nt < 4; nt++)
                mma16816(acc[mt][nt], ah[mt], bh[nt]);
        #pragma unroll
        for (int mt = 0; mt < 4; mt++)
            #pragma unroll
            for (int nt = 0; nt < 4; nt++)
                mma16816(acc[mt][nt], ah[mt], bl[nt]);
        #pragma unroll
        for (int mt = 0; mt < 4; mt++)
            #pragma unroll
            for (int nt = 0; nt < 4; nt++)
                mma16816(acc[mt][nt], al[mt], bh[nt]);

        // issue stage it+3 into buffer (it-1)&3 (dead since this iter's barrier)
        const int nx = it + 3;
        if (nx < niter) {
            const uint32_t db = smem_base + (uint32_t)(nx & 3) * STAGE_BYTES;
            const int k0 = nx << 4;
            #pragma unroll
            for (int t = 0; t < 4; t++)
                cp_async16(db + (uint32_t)t * TILE_BYTES + st_off, srcs[t] + g_off + k0);
        }
        CP_COMMIT();
    }

    // Epilogue: direct fp32 stores
    #pragma unroll
    for (int mt = 0; mt < 4; mt++) {
        #pragma unroll
        for (int nt = 0; nt < 4; nt++) {
            const int r = bm + mbase + mt * 16 + g;
            const int col = bn + nbase + nt * 8 + tg * 2;
            float2 v0; v0.x = acc[mt][nt][0]; v0.y = acc[mt][nt][1];
            float2 v1; v1.x = acc[mt][nt][2]; v1.y = acc[mt][nt][3];
            *(float2*)&C[(size_t)r * N + col] = v0;
            *(float2*)&C[(size_t)(r + 8) * N + col] = v1;
        }
    }
}

// ---------------------------------------------------------------------------
// Tensor-core sliding-window attention (bf16x3), fused output split.
// (unchanged from round 7)
// ---------------------------------------------------------------------------
#define AT_KH 0
#define AT_KL 24576
#define AT_VH 49152
#define AT_VL 73728
#define AT_PN 98304
#define AT_RM 99072
#define AT_RS 99584
#define ATTN_SMEM 100096

__global__ __launch_bounds__(256, 2) void attn_mma_kernel(
    const float* __restrict__ qkv, const float* __restrict__ pmask,
    __nv_bfloat16* __restrict__ ohi, __nv_bfloat16* __restrict__ olo)
{
    extern __shared__ __align__(128) char smem[];
    const uint32_t sb = smem_u32(smem);
    float* PNf = (float*)(smem + AT_PN);
    float* RMf = (float*)(smem + AT_RM);
    float* RSf = (float*)(smem + AT_RS);

    const int qt = blockIdx.x, h = blockIdx.y, b = blockIdx.z;
    const int q0 = qt * 64;
    const int kstart = q0 - 64;
    const int tid = threadIdx.x;
    const int wid = tid >> 5, lane = tid & 31;
    const int g = lane >> 2, tg = lane & 3;

    const int wm1 = wid >> 1, wn1 = wid & 1;
    uint32_t qh[4][4], ql[4][4];
    {
        const float* qr0 = qkv + ((size_t)(b * SS + q0 + wm1 * 16 + g)) * (3 * DD) + h * HDIM;
        const float* qr8 = qr0 + (size_t)8 * (3 * DD);
        #pragma unroll
        for (int ks = 0; ks < 4; ks++) {
            float2 x0 = *(const float2*)(qr0 + ks * 16 + tg * 2);
            float2 x1 = *(const float2*)(qr8 + ks * 16 + tg * 2);
            float2 x2 = *(const float2*)(qr0 + ks * 16 + 8 + tg * 2);
            float2 x3 = *(const float2*)(qr8 + ks * 16 + 8 + tg * 2);
            split2(x0.x, x0.y, qh[ks][0], ql[ks][0]);
            split2(x1.x, x1.y, qh[ks][1], ql[ks][1]);
            split2(x2.x, x2.y, qh[ks][2], ql[ks][2]);
            split2(x3.x, x3.y, qh[ks][3], ql[ks][3]);
        }
    }

    for (int idx = tid; idx < 192 * 8; idx += 256) {
        const int key = idx >> 3, u = idx & 7;
        const int gk = kstart + key;
        float4 kv0, kv1, vv0, vv1;
        if (gk >= 0 && gk < SS) {
            const float* base = qkv + ((size_t)(b * SS + gk)) * (3 * DD) + h * HDIM + u * 8;
            kv0 = *(const float4*)(base + DD);
            kv1 = *(const float4*)(base + DD + 4);
            vv0 = *(const float4*)(base + 2 * DD);
            vv1 = *(const float4*)(base + 2 * DD + 4);
        } else {
            kv0 = kv1 = vv0 = vv1 = make_float4(0.f, 0.f, 0.f, 0.f);
        }
        const uint32_t swo = (uint32_t)(key * 128 + ((u * 16) ^ ((key & 7) << 4)));
        uint4 hi4, lo4;
        split2(kv0.x, kv0.y, hi4.x, lo4.x);
        split2(kv0.z, kv0.w, hi4.y, lo4.y);
        split2(kv1.x, kv1.y, hi4.z, lo4.z);
        split2(kv1.z, kv1.w, hi4.w, lo4.w);
        *(uint4*)(smem + AT_KH + swo) = hi4;
        *(uint4*)(smem + AT_KL + swo) = lo4;
        split2(vv0.x, vv0.y, hi4.x, lo4.x);
        split2(vv0.z, vv0.w, hi4.y, lo4.y);
        split2(vv1.x, vv1.y, hi4.z, lo4.z);
        split2(vv1.z, vv1.w, hi4.w, lo4.w);
        *(uint4*)(smem + AT_VH + swo) = hi4;
        *(uint4*)(smem + AT_VL + swo) = lo4;
    }
    for (int j = tid; j < 192; j += 256) {
        const int gk = kstart + j;
        PNf[j] = (gk >= 0 && gk < SS) ? (1.0f - pmask[b * SS + gk]) * NEGV : -1e30f;
    }
    __syncthreads();

    float acc[12][4];
    #pragma unroll
    for (int nt = 0; nt < 12; nt++)
        #pragma unroll
        for (int c = 0; c < 4; c++) acc[nt][c] = 0.f;

    #pragma unroll
    for (int ks = 0; ks < 4; ks++) {
        #pragma unroll
        for (int nt = 0; nt < 12; nt++) {
            const int brow = wn1 * 96 + nt * 8 + (lane & 7);
            const uint32_t bo = (uint32_t)(brow * 128 +
                ((ks * 32 + ((lane >> 3) & 1) * 16) ^ ((lane & 7) << 4)));
            uint32_t bh[2], bl[2];
            LDSM_X2(bh[0], bh[1], sb + AT_KH + bo);
            LDSM_X2(bl[0], bl[1], sb + AT_KL + bo);
            mma16816(acc[nt], qh[ks], bh);
            mma16816(acc[nt], qh[ks], bl);
            mma16816(acc[nt], ql[ks], bh);
        }
    }

    const int r0 = wm1 * 16 + g;
    const int r1 = r0 + 8;
    #pragma unroll
    for (int nt = 0; nt < 12; nt++) {
        const int j0 = wn1 * 96 + nt * 8 + tg * 2;
        #pragma unroll
        for (int e = 0; e < 4; e++) {
            const int j = j0 + (e & 1);
            const int rr = (e < 2) ? r0 : r1;
            const int diff = j - rr;
            acc[nt][e] = (diff >= 0 && diff <= 128)
                       ? acc[nt][e] * 0.125f + PNf[j] : -1e30f;
        }
    }

    float m0 = -1e30f, m1 = -1e30f;
    #pragma unroll
    for (int nt = 0; nt < 12; nt++) {
        m0 = fmaxf(m0, fmaxf(acc[nt][0], acc[nt][1]));
        m1 = fmaxf(m1, fmaxf(acc[nt][2], acc[nt][3]));
    }
    #pragma unroll
    for (int o = 1; o <= 2; o <<= 1) {
        m0 = fmaxf(m0, __shfl_xor_sync(0xffffffffu, m0, o));
        m1 = fmaxf(m1, __shfl_xor_sync(0xffffffffu, m1, o));
    }
    if (tg == 0) { RMf[r0 * 2 + wn1] = m0; RMf[r1 * 2 + wn1] = m1; }
    __syncthreads();
    m0 = fmaxf(RMf[r0 * 2], RMf[r0 * 2 + 1]);
    m1 = fmaxf(RMf[r1 * 2], RMf[r1 * 2 + 1]);

    float s0 = 0.f, s1 = 0.f;
    #pragma unroll
    for (int nt = 0; nt < 12; nt++) {
        acc[nt][0] = __expf(acc[nt][0] - m0);
        acc[nt][1] = __expf(acc[nt][1] - m0);
        acc[nt][2] = __expf(acc[nt][2] - m1);
        acc[nt][3] = __expf(acc[nt][3] - m1);
        s0 += acc[nt][0] + acc[nt][1];
        s1 += acc[nt][2] + acc[nt][3];
    }
    #pragma unroll
    for (int o = 1; o <= 2; o <<= 1) {
        s0 += __shfl_xor_sync(0xffffffffu, s0, o);
        s1 += __shfl_xor_sync(0xffffffffu, s1, o);
    }
    if (tg == 0) { RSf[r0 * 2 + wn1] = s0; RSf[r1 * 2 + wn1] = s1; }
    __syncthreads();
    const float inv0 = 1.f / (RSf[r0 * 2] + RSf[r0 * 2 + 1]);
    const float inv1 = 1.f / (RSf[r1 * 2] + RSf[r1 * 2 + 1]);

    #pragma unroll
    for (int nt = 0; nt < 12; nt++) {
        const int j0 = wn1 * 96 + nt * 8 + tg * 2;
        uint32_t hi, lo;
        split2(acc[nt][0] * inv0, acc[nt][1] * inv0, hi, lo);
        uint32_t o0 = (uint32_t)(r0 * 384 + ((j0 * 2) ^ ((r0 & 7) << 4)));
        *(uint32_t*)(smem + AT_KH + o0) = hi;
        *(uint32_t*)(smem + AT_KL + o0) = lo;
        split2(acc[nt][2] * inv1, acc[nt][3] * inv1, hi, lo);
        uint32_t o1 = (uint32_t)(r1 * 384 + ((j0 * 2) ^ ((r1 & 7) << 4)));
        *(uint32_t*)(smem + AT_KH + o1) = hi;
        *(uint32_t*)(smem + AT_KL + o1) = lo;
    }
    __syncthreads();

    const int wm3 = wm1, wn3 = wn1;
    float oacc[4][4];
    #pragma unroll
    for (int nt = 0; nt < 4; nt++)
        #pragma unroll
        for (int c = 0; c < 4; c++) oacc[nt][c] = 0.f;

    #pragma unroll
    for (int ks = 0; ks < 12; ks++) {
        const int prow = wm3 * 16 + (lane & 15);
        const uint32_t po = (uint32_t)(prow * 384 +
            ((ks * 32 + (lane >> 4) * 16) ^ ((prow & 7) << 4)));
        uint32_t ph[4], pl[4];
        LDSM_X4(ph[0], ph[1], ph[2], ph[3], sb + AT_KH + po);
        LDSM_X4(pl[0], pl[1], pl[2], pl[3], sb + AT_KL + po);
        #pragma unroll
        for (int nt = 0; nt < 4; nt++) {
            const int vrow = ks * 16 + (lane & 15);
            const uint32_t vo = (uint32_t)(vrow * 128 +
                (((wn3 * 32 + nt * 8) * 2) ^ ((vrow & 7) << 4)));
            uint32_t vh[2], vl[2];
            LDSM_X2T(vh[0], vh[1], sb + AT_VH + vo);
            LDSM_X2T(vl[0], vl[1], sb + AT_VL + vo);
            mma16816(oacc[nt], ph, vh);
            mma16816(oacc[nt], ph, vl);
            mma16816(oacc[nt], pl, vh);
        }
    }

    #pragma unroll
    for (int nt = 0; nt < 4; nt++) {
        const int gq0 = q0 + wm3 * 16 + g;
        const int col = h * HDIM + wn3 * 32 + nt * 8 + tg * 2;
        uint32_t hi, lo;
        size_t off = ((size_t)(b * SS + gq0)) * DD + col;
        split2(oacc[nt][0], oacc[nt][1], hi, lo);
        *(uint32_t*)(ohi + off) = hi;
        *(uint32_t*)(olo + off) = lo;
        off += (size_t)8 * DD;
        split2(oacc[nt][2], oacc[nt][3], hi, lo);
        *(uint32_t*)(ohi + off) = hi;
        *(uint32_t*)(olo + off) = lo;
    }
}

// ---------------------------------------------------------------------------
extern "C" void kernel_launch(void* const* d_in, const int* in_sizes, int n_in,
                              void* d_out, int out_size)
{
    const float* x    = (const float*)d_in[0];
    const float* pm   = (const float*)d_in[1];
    const float* Wqkv = (const float*)d_in[2];
    const float* Wo   = (const float*)d_in[3];
    float* out = (float*)d_out;

    float* qkv_p;
    __nv_bfloat16 *xhi, *xlo, *wqh, *wql, *woh, *wol, *ahi, *alo;
    cudaGetSymbolAddress((void**)&qkv_p, g_qkv);
    cudaGetSymbolAddress((void**)&xhi, g_xhi);
    cudaGetSymbolAddress((void**)&xlo, g_xlo);
    cudaGetSymbolAddress((void**)&wqh, g_wqh);
    cudaGetSymbolAddress((void**)&wql, g_wql);
    cudaGetSymbolAddress((void**)&woh, g_woh);
    cudaGetSymbolAddress((void**)&wol, g_wol);
    cudaGetSymbolAddress((void**)&ahi, g_ahi);
    cudaGetSymbolAddress((void**)&alo, g_alo);

    const int M = BB * SS;            // 4096
    const int nx = M * DD;            // 3.1M

    static bool attr_done = false;
    if (!attr_done) {
        cudaFuncSetAttribute(gemm_bf16x3_kernel,
                             cudaFuncAttributeMaxDynamicSharedMemorySize, GEMM_SMEM);
        cudaFuncSetAttribute(attn_mma_kernel,
                             cudaFuncAttributeMaxDynamicSharedMemorySize, ATTN_SMEM);
        attr_done = true;
    }

    // Input conversions
    split_kernel<<<(nx + 255) / 256, 256>>>(x, xhi, xlo, nx);
    splitT_kernel<<<dim3(3 * DD / 32, DD / 32), dim3(32, 8)>>>(Wqkv, wqh, wql, DD, 3 * DD);
    splitT_kernel<<<dim3(DD / 32, DD / 32), dim3(32, 8)>>>(Wo, woh, wol, DD, DD);

    // 1) QKV projection (tensor cores)
    gemm_bf16x3_kernel<<<dim3(3 * DD / 128, M / 128), 256, GEMM_SMEM>>>(
        xhi, xlo, wqh, wql, qkv_p, M, 3 * DD, DD);

    // 2) Sliding-window attention (tensor cores), writes bf16 hi/lo directly
    attn_mma_kernel<<<dim3(SS / 64, HH, BB), 256, ATTN_SMEM>>>(qkv_p, pm, ahi, alo);

    // 3) Output projection (tensor cores)
    gemm_bf16x3_kernel<<<dim3(DD / 128, M / 128), 256, GEMM_SMEM>>>(
        ahi, alo, woh, wol, out, M, DD, DD);
}